// round 2
// baseline (speedup 1.0000x reference)
#include <cuda_runtime.h>
#include <cstdint>

#define NBODY      8192
#define BLOCK      256
#define NSPLIT     16
#define JCHUNK     (NBODY / NSPLIT)   // 512 bodies per block = 256 pairs
#define NPAIRS     (JCHUNK / 2)       // 256
#define SOFT2      (0.01f * 0.01f)

__device__ __forceinline__ uint64_t f2_add(uint64_t a, uint64_t b) {
    uint64_t r; asm("add.rn.f32x2 %0, %1, %2;" : "=l"(r) : "l"(a), "l"(b)); return r;
}
__device__ __forceinline__ uint64_t f2_mul(uint64_t a, uint64_t b) {
    uint64_t r; asm("mul.rn.f32x2 %0, %1, %2;" : "=l"(r) : "l"(a), "l"(b)); return r;
}
__device__ __forceinline__ uint64_t f2_fma(uint64_t a, uint64_t b, uint64_t c) {
    uint64_t r; asm("fma.rn.f32x2 %0, %1, %2, %3;" : "=l"(r) : "l"(a), "l"(b), "l"(c)); return r;
}
__device__ __forceinline__ uint64_t f2_pack(float lo, float hi) {
    uint64_t r;
    asm("mov.b64 %0, {%1, %2};" : "=l"(r) : "f"(lo), "f"(hi));
    return r;
}
__device__ __forceinline__ void f2_unpack(float& lo, float& hi, uint64_t v) {
    asm("mov.b64 {%0, %1}, %2;" : "=f"(lo), "=f"(hi) : "l"(v));
}

__global__ void zero_out_kernel(float* out, int n) {
    int idx = blockIdx.x * blockDim.x + threadIdx.x;
    if (idx < n) out[idx] = 0.0f;
}

__global__ __launch_bounds__(BLOCK)
void nbody_kernel(const float* __restrict__ pos,
                  const float* __restrict__ mass,
                  float* __restrict__ out) {
    const int tid = threadIdx.x;
    const int i   = blockIdx.x * BLOCK + tid;

    const float xi = pos[3 * i + 0];
    const float yi = pos[3 * i + 1];
    const float zi = pos[3 * i + 2];

    // SoA shared tiles: each float2 holds bodies (2k, 2k+1) -> pre-packed f32x2
    __shared__ float2 shx[NPAIRS];
    __shared__ float2 shy[NPAIRS];
    __shared__ float2 shz[NPAIRS];
    __shared__ float2 shm[NPAIRS];

    {
        const int j = blockIdx.y * JCHUNK + 2 * tid;   // tid < 256 == NPAIRS
        shx[tid] = make_float2(pos[3 * j + 0], pos[3 * j + 3]);
        shy[tid] = make_float2(pos[3 * j + 1], pos[3 * j + 4]);
        shz[tid] = make_float2(pos[3 * j + 2], pos[3 * j + 5]);
        shm[tid] = make_float2(mass[j], mass[j + 1]);
    }
    __syncthreads();

    const uint64_t nxi = f2_pack(-xi, -xi);
    const uint64_t nyi = f2_pack(-yi, -yi);
    const uint64_t nzi = f2_pack(-zi, -zi);
    const uint64_t s2p = f2_pack(SOFT2, SOFT2);

    uint64_t axp = 0ull, ayp = 0ull, azp = 0ull;   // packed (0.0f, 0.0f)

    const uint64_t* __restrict__ px = reinterpret_cast<const uint64_t*>(shx);
    const uint64_t* __restrict__ py = reinterpret_cast<const uint64_t*>(shy);
    const uint64_t* __restrict__ pz = reinterpret_cast<const uint64_t*>(shz);
    const uint64_t* __restrict__ pm = reinterpret_cast<const uint64_t*>(shm);

    #pragma unroll 8
    for (int k = 0; k < NPAIRS; k++) {
        const uint64_t xp = px[k];   // LDS.64, warp-broadcast
        const uint64_t yp = py[k];
        const uint64_t zp = pz[k];
        const uint64_t mp = pm[k];

        const uint64_t dx = f2_add(xp, nxi);
        const uint64_t dy = f2_add(yp, nyi);
        const uint64_t dz = f2_add(zp, nzi);

        uint64_t d2 = s2p;
        d2 = f2_fma(dx, dx, d2);
        d2 = f2_fma(dy, dy, d2);
        d2 = f2_fma(dz, dz, d2);

        float d0, d1;
        f2_unpack(d0, d1, d2);
        const float i0 = rsqrtf(d0);    // MUFU.RSQ
        const float i1 = rsqrtf(d1);
        const uint64_t invp = f2_pack(i0, i1);

        const uint64_t inv2  = f2_mul(invp, invp);
        const uint64_t minv2 = f2_mul(mp, inv2);
        const uint64_t w     = f2_mul(minv2, invp);   // m_j * d2^(-3/2)

        axp = f2_fma(w, dx, axp);
        ayp = f2_fma(w, dy, ayp);
        azp = f2_fma(w, dz, azp);
    }

    float axl, axh, ayl, ayh, azl, azh;
    f2_unpack(axl, axh, axp);
    f2_unpack(ayl, ayh, ayp);
    f2_unpack(azl, azh, azp);

    atomicAdd(&out[3 * i + 0], axl + axh);
    atomicAdd(&out[3 * i + 1], ayl + ayh);
    atomicAdd(&out[3 * i + 2], azl + azh);
}

extern "C" void kernel_launch(void* const* d_in, const int* in_sizes, int n_in,
                              void* d_out, int out_size) {
    const float* pos  = (const float*)d_in[0];   // (8192, 3) float32
    const float* mass = (const float*)d_in[1];   // (8192,)   float32
    float* out        = (float*)d_out;           // (8192, 3) float32

    zero_out_kernel<<<(NBODY * 3 + 255) / 256, 256>>>(out, NBODY * 3);

    dim3 grid(NBODY / BLOCK, NSPLIT);
    nbody_kernel<<<grid, BLOCK>>>(pos, mass, out);
}

// round 3
// speedup vs baseline: 1.1118x; 1.1118x over previous
#include <cuda_runtime.h>
#include <cstdint>

#define NBODY      8192
#define BLOCK      128
#define NSPLIT     32
#define JCHUNK     (NBODY / NSPLIT)   // 256 bodies per block
#define NPAIRS     (JCHUNK / 2)       // 128 packed pairs
#define SOFT2      (0.01f * 0.01f)

__device__ __forceinline__ uint64_t f2_add(uint64_t a, uint64_t b) {
    uint64_t r; asm("add.rn.f32x2 %0, %1, %2;" : "=l"(r) : "l"(a), "l"(b)); return r;
}
__device__ __forceinline__ uint64_t f2_mul(uint64_t a, uint64_t b) {
    uint64_t r; asm("mul.rn.f32x2 %0, %1, %2;" : "=l"(r) : "l"(a), "l"(b)); return r;
}
__device__ __forceinline__ uint64_t f2_fma(uint64_t a, uint64_t b, uint64_t c) {
    uint64_t r; asm("fma.rn.f32x2 %0, %1, %2, %3;" : "=l"(r) : "l"(a), "l"(b), "l"(c)); return r;
}
__device__ __forceinline__ uint64_t f2_pack(float lo, float hi) {
    uint64_t r;
    asm("mov.b64 %0, {%1, %2};" : "=l"(r) : "f"(lo), "f"(hi));
    return r;
}
__device__ __forceinline__ void f2_unpack(float& lo, float& hi, uint64_t v) {
    asm("mov.b64 {%0, %1}, %2;" : "=f"(lo), "=f"(hi) : "l"(v));
}

__global__ void zero_out_kernel(float* out, int n) {
    int idx = blockIdx.x * blockDim.x + threadIdx.x;
    if (idx < n) out[idx] = 0.0f;
}

__global__ __launch_bounds__(BLOCK, 12)
void nbody_kernel(const float* __restrict__ pos,
                  const float* __restrict__ mass,
                  float* __restrict__ out) {
    const int tid = threadIdx.x;
    const int i   = blockIdx.x * BLOCK + tid;

    const float xi = pos[3 * i + 0];
    const float yi = pos[3 * i + 1];
    const float zi = pos[3 * i + 2];

    // SoA shared tiles: each float2 holds bodies (2k, 2k+1) -> pre-packed f32x2
    __shared__ float2 shx[NPAIRS];
    __shared__ float2 shy[NPAIRS];
    __shared__ float2 shz[NPAIRS];
    __shared__ float2 shm[NPAIRS];

    if (tid < NPAIRS) {
        const int j = blockIdx.y * JCHUNK + 2 * tid;
        shx[tid] = make_float2(pos[3 * j + 0], pos[3 * j + 3]);
        shy[tid] = make_float2(pos[3 * j + 1], pos[3 * j + 4]);
        shz[tid] = make_float2(pos[3 * j + 2], pos[3 * j + 5]);
        shm[tid] = make_float2(mass[j], mass[j + 1]);
    }
    __syncthreads();

    const uint64_t nxi = f2_pack(-xi, -xi);
    const uint64_t nyi = f2_pack(-yi, -yi);
    const uint64_t nzi = f2_pack(-zi, -zi);
    const uint64_t s2p = f2_pack(SOFT2, SOFT2);

    uint64_t axp = 0ull, ayp = 0ull, azp = 0ull;   // packed (0.0f, 0.0f)

    const uint64_t* __restrict__ px = reinterpret_cast<const uint64_t*>(shx);
    const uint64_t* __restrict__ py = reinterpret_cast<const uint64_t*>(shy);
    const uint64_t* __restrict__ pz = reinterpret_cast<const uint64_t*>(shz);
    const uint64_t* __restrict__ pm = reinterpret_cast<const uint64_t*>(shm);

    #pragma unroll 8
    for (int k = 0; k < NPAIRS; k++) {
        const uint64_t xp = px[k];   // LDS.64, warp-broadcast
        const uint64_t yp = py[k];
        const uint64_t zp = pz[k];
        const uint64_t mp = pm[k];

        const uint64_t dx = f2_add(xp, nxi);
        const uint64_t dy = f2_add(yp, nyi);
        const uint64_t dz = f2_add(zp, nzi);

        uint64_t d2 = s2p;
        d2 = f2_fma(dx, dx, d2);
        d2 = f2_fma(dy, dy, d2);
        d2 = f2_fma(dz, dz, d2);

        float d0, d1;
        f2_unpack(d0, d1, d2);
        const float i0 = rsqrtf(d0);    // MUFU.RSQ
        const float i1 = rsqrtf(d1);
        const uint64_t invp = f2_pack(i0, i1);

        const uint64_t inv2  = f2_mul(invp, invp);
        const uint64_t minv2 = f2_mul(mp, inv2);
        const uint64_t w     = f2_mul(minv2, invp);   // m_j * d2^(-3/2)

        axp = f2_fma(w, dx, axp);
        ayp = f2_fma(w, dy, ayp);
        azp = f2_fma(w, dz, azp);
    }

    float axl, axh, ayl, ayh, azl, azh;
    f2_unpack(axl, axh, axp);
    f2_unpack(ayl, ayh, ayp);
    f2_unpack(azl, azh, azp);

    atomicAdd(&out[3 * i + 0], axl + axh);
    atomicAdd(&out[3 * i + 1], ayl + ayh);
    atomicAdd(&out[3 * i + 2], azl + azh);
}

extern "C" void kernel_launch(void* const* d_in, const int* in_sizes, int n_in,
                              void* d_out, int out_size) {
    const float* pos  = (const float*)d_in[0];   // (8192, 3) float32
    const float* mass = (const float*)d_in[1];   // (8192,)   float32
    float* out        = (float*)d_out;           // (8192, 3) float32

    zero_out_kernel<<<(NBODY * 3 + 255) / 256, 256>>>(out, NBODY * 3);

    dim3 grid(NBODY / BLOCK, NSPLIT);
    nbody_kernel<<<grid, BLOCK>>>(pos, mass, out);
}